// round 13
// baseline (speedup 1.0000x reference)
#include <cuda_runtime.h>
#include <cuda_bf16.h>
#include <math.h>
#include <stdint.h>

// ---------------- problem constants ----------------
#define NNODES 65536
#define NGRAPH 512
#define NPER   128
#define NEDGE  655360
#define FIN    128
#define KTOP   32
#define NOUT   27

// ---------------- device scratch (no allocs allowed) ----------------
__device__ float g_h[(size_t)NNODES * 256];   // concat features x1|x2|x3|x4
__device__ float g_xw[(size_t)NNODES * 128];  // per-layer X@W scratch
__device__ float g_dinv[NNODES];
__device__ int   g_degI[NNODES];
__device__ int   g_colptr[NNODES + 1];
__device__ int   g_cursor[NNODES];
__device__ int   g_srcs[NEDGE];
__device__ float g_coef[NEDGE];
__device__ float g_keys[NNODES];              // compact sort keys (h[:,255])
__device__ int   g_bsum[64];

// ---------------- f32x2 packed helpers (Blackwell) ----------------
__device__ __forceinline__ void fma2(uint64_t& d, uint64_t a, uint64_t b) {
    asm("fma.rn.f32x2 %0, %1, %2, %0;" : "+l"(d) : "l"(a), "l"(b));
}
__device__ __forceinline__ uint64_t dup2(float a) {
    uint32_t au = __float_as_uint(a);
    uint64_t r;
    asm("mov.b64 %0, {%1, %1};" : "=l"(r) : "r"(au));
    return r;
}

// ---------------- prep kernels ----------------
__global__ void hist_k(const int4* __restrict__ col4) {
    int i = blockIdx.x * blockDim.x + threadIdx.x;
    if (i < NEDGE / 4) {
        int4 c = col4[i];
        atomicAdd(&g_degI[c.x], 1);
        atomicAdd(&g_degI[c.y], 1);
        atomicAdd(&g_degI[c.z], 1);
        atomicAdd(&g_degI[c.w], 1);
    }
}

// ---- parallel exclusive scan over 65536 bins (+ fused dinv & cursor zero) ----
__global__ void scan1_k() {   // 64 blocks x 1024
    __shared__ int s[1024];
    int t = threadIdx.x;
    int idx = blockIdx.x * 1024 + t;
    int v = g_degI[idx];
    g_cursor[idx] = 0;
    g_dinv[idx] = rsqrtf((float)v + 1.0f);
    s[t] = v;
    __syncthreads();
    for (int off = 1; off < 1024; off <<= 1) {
        int tmp = (t >= off) ? s[t - off] : 0;
        __syncthreads();
        s[t] += tmp;
        __syncthreads();
    }
    g_colptr[idx] = s[t] - v;                 // exclusive within block
    if (t == 1023) g_bsum[blockIdx.x] = s[t]; // block total
}

// scan3: each block locally re-scans the 64 block sums (fused scan2)
__global__ void scan3_k() {   // 64 blocks x 1024
    __shared__ int s[64];
    int t = threadIdx.x;
    if (t < 64) s[t] = g_bsum[t];
    __syncthreads();
    for (int off = 1; off < 64; off <<= 1) {
        int v = (t >= off && t < 64) ? s[t - off] : 0;
        __syncthreads();
        if (t < 64) s[t] += v;
        __syncthreads();
    }
    int boff = (blockIdx.x == 0) ? 0 : s[blockIdx.x - 1];
    int idx = blockIdx.x * 1024 + t;
    g_colptr[idx] += boff;
    if (blockIdx.x == 0 && t == 0) g_colptr[NNODES] = s[63];
}

// scalar scatter (latency-bound: keep max thread-level MLP)
__global__ void scatter_k(const int* __restrict__ row, const int* __restrict__ col) {
    int e = blockIdx.x * blockDim.x + threadIdx.x;
    if (e < NEDGE) {
        int c = col[e];
        int r = row[e];
        int p = atomicAdd(&g_cursor[c], 1);
        int pos = g_colptr[c] + p;
        g_srcs[pos] = r;
        g_coef[pos] = g_dinv[r] * g_dinv[c];
    }
}

// ---------------- SGEMM: C[M,TN] = A[M,K](lda) @ B[K,TN] ----------------
// 128xTN tile, 256 threads, packed fma.rn.f32x2 inner loop, double-buffered.
template <int TN, int K>
__global__ __launch_bounds__(256, 2) void gemm_k(const float* __restrict__ A, int lda,
                                                 const float* __restrict__ B,
                                                 float* __restrict__ C)
{
    constexpr int RN = TN / 16;          // 8, 4, or 2
    constexpr int RNH = RN / 2;          // 4, 2, or 1 packed pairs
    constexpr int BELEM = 8 * TN;
    __shared__ float As[2][8][128];
    __shared__ float Bs[2][8][TN];

    const int tid = threadIdx.x;
    const int tx = tid & 15;
    const int ty = tid >> 4;
    const int rowBase = blockIdx.x * 128;

    const int ar = tid >> 1;
    const int akk = (tid & 1) * 4;
    const int bthreads = BELEM / 4;
    const int bk = (tid * 4) / TN;
    const int bn = (tid * 4) % TN;
    const bool bload = tid < bthreads;

    uint64_t acc2[8][RNH];
#pragma unroll
    for (int i = 0; i < 8; i++)
#pragma unroll
        for (int j = 0; j < RNH; j++) acc2[i][j] = 0ull;

    {
        float4 av = *(const float4*)(A + (size_t)(rowBase + ar) * lda + akk);
        As[0][akk + 0][ar] = av.x; As[0][akk + 1][ar] = av.y;
        As[0][akk + 2][ar] = av.z; As[0][akk + 3][ar] = av.w;
        if (bload) {
            float4 bv = *(const float4*)(B + (size_t)bk * TN + bn);
            *(float4*)&Bs[0][bk][bn] = bv;
        }
    }
    __syncthreads();

    int buf = 0;
#pragma unroll
    for (int k0 = 0; k0 < K; k0 += 8) {
        float4 av; float4 bv;
        const bool more = (k0 + 8) < K;
        if (more) {
            av = *(const float4*)(A + (size_t)(rowBase + ar) * lda + k0 + 8 + akk);
            if (bload) bv = *(const float4*)(B + (size_t)(k0 + 8 + bk) * TN + bn);
        }
#pragma unroll
        for (int k = 0; k < 8; k++) {
            float a[8];
            *(float4*)(a)     = *(const float4*)&As[buf][k][ty * 8];
            *(float4*)(a + 4) = *(const float4*)&As[buf][k][ty * 8 + 4];
            uint64_t b2[RNH];
            const uint64_t* bp = (const uint64_t*)&Bs[buf][k][tx * RN];
#pragma unroll
            for (int j = 0; j < RNH; j++) b2[j] = bp[j];
#pragma unroll
            for (int i = 0; i < 8; i++) {
                uint64_t a2 = dup2(a[i]);
#pragma unroll
                for (int j = 0; j < RNH; j++) fma2(acc2[i][j], a2, b2[j]);
            }
        }
        if (more) {
            int nb = buf ^ 1;
            As[nb][akk + 0][ar] = av.x; As[nb][akk + 1][ar] = av.y;
            As[nb][akk + 2][ar] = av.z; As[nb][akk + 3][ar] = av.w;
            if (bload) *(float4*)&Bs[nb][bk][bn] = bv;
            __syncthreads();
            buf = nb;
        }
    }

#pragma unroll
    for (int i = 0; i < 8; i++) {
        float* cp = C + (size_t)(rowBase + ty * 8 + i) * TN + tx * RN;
        if (RNH == 4) {
            *(float4*)(cp)     = *(const float4*)&acc2[i][0];
            *(float4*)(cp + 4) = *(const float4*)&acc2[i][2];
        } else if (RNH == 2) {
            *(float4*)(cp) = *(const float4*)&acc2[i][0];
        } else {
            *(uint64_t*)(cp) = acc2[i][0];
        }
    }
}

// ---------------- aggregation + self-loop + bias + tanh ----------------
// warp per node; V = fout/32 features per lane; 8-edge batched gathers (MLP=8).
// NOTE: exact tanhf is REQUIRED — sort keys are tanh outputs; any approximation
// flips argsort order in saturated regions (proven: rel_err 1e-2 in R10).
template <int V, bool WRITE_KEYS>
__global__ void agg_tanh_k(const float* __restrict__ xw,
                           const float* __restrict__ bias,
                           float* __restrict__ hout)   // h + column offset, row stride 256
{
    const int FO = V * 32;
    int gw = (blockIdx.x * blockDim.x + threadIdx.x) >> 5;
    if (gw >= NNODES) return;
    int lane = threadIdx.x & 31;
    int f0 = lane * V;

    float di = g_dinv[gw];
    float acc[V];
    {
        const float* p = xw + (size_t)gw * FO + f0;
        float d2 = di * di;
        if (V == 4) {
            float4 v = *(const float4*)p;
            acc[0] = d2 * v.x; acc[1] = d2 * v.y; acc[2] = d2 * v.z; acc[3] = d2 * v.w;
        } else if (V == 2) {
            float2 v = *(const float2*)p;
            acc[0] = d2 * v.x; acc[1] = d2 * v.y;
        } else {
            acc[0] = d2 * p[0];
        }
    }
    int e0 = g_colptr[gw], e1 = g_colptr[gw + 1];
    int e = e0;

    // 8-edge batches: all metadata loads, then all row gathers, then FMAs
    for (; e + 8 <= e1; e += 8) {
        int s[8]; float c[8];
#pragma unroll
        for (int q = 0; q < 8; q++) { s[q] = g_srcs[e + q]; c[q] = g_coef[e + q]; }
        if (V == 4) {
            float4 v[8];
#pragma unroll
            for (int q = 0; q < 8; q++) v[q] = *(const float4*)(xw + (size_t)s[q] * FO + f0);
#pragma unroll
            for (int q = 0; q < 8; q++) {
                acc[0] = fmaf(c[q], v[q].x, acc[0]); acc[1] = fmaf(c[q], v[q].y, acc[1]);
                acc[2] = fmaf(c[q], v[q].z, acc[2]); acc[3] = fmaf(c[q], v[q].w, acc[3]);
            }
        } else if (V == 2) {
            float2 v[8];
#pragma unroll
            for (int q = 0; q < 8; q++) v[q] = *(const float2*)(xw + (size_t)s[q] * FO + f0);
#pragma unroll
            for (int q = 0; q < 8; q++) {
                acc[0] = fmaf(c[q], v[q].x, acc[0]); acc[1] = fmaf(c[q], v[q].y, acc[1]);
            }
        } else {
            float v[8];
#pragma unroll
            for (int q = 0; q < 8; q++) v[q] = xw[(size_t)s[q] * FO + f0];
#pragma unroll
            for (int q = 0; q < 8; q++) acc[0] = fmaf(c[q], v[q], acc[0]);
        }
    }
    // 4-edge batch
    for (; e + 4 <= e1; e += 4) {
        int s[4]; float c[4];
#pragma unroll
        for (int q = 0; q < 4; q++) { s[q] = g_srcs[e + q]; c[q] = g_coef[e + q]; }
        if (V == 4) {
            float4 v[4];
#pragma unroll
            for (int q = 0; q < 4; q++) v[q] = *(const float4*)(xw + (size_t)s[q] * FO + f0);
#pragma unroll
            for (int q = 0; q < 4; q++) {
                acc[0] = fmaf(c[q], v[q].x, acc[0]); acc[1] = fmaf(c[q], v[q].y, acc[1]);
                acc[2] = fmaf(c[q], v[q].z, acc[2]); acc[3] = fmaf(c[q], v[q].w, acc[3]);
            }
        } else if (V == 2) {
            float2 v[4];
#pragma unroll
            for (int q = 0; q < 4; q++) v[q] = *(const float2*)(xw + (size_t)s[q] * FO + f0);
#pragma unroll
            for (int q = 0; q < 4; q++) {
                acc[0] = fmaf(c[q], v[q].x, acc[0]); acc[1] = fmaf(c[q], v[q].y, acc[1]);
            }
        } else {
            float v[4];
#pragma unroll
            for (int q = 0; q < 4; q++) v[q] = xw[(size_t)s[q] * FO + f0];
#pragma unroll
            for (int q = 0; q < 4; q++) acc[0] = fmaf(c[q], v[q], acc[0]);
        }
    }
    // scalar remainder
    for (; e < e1; e++) {
        int s = g_srcs[e];
        float c = g_coef[e];
        const float* p = xw + (size_t)s * FO + f0;
        if (V == 4) {
            float4 v = *(const float4*)p;
            acc[0] = fmaf(c, v.x, acc[0]); acc[1] = fmaf(c, v.y, acc[1]);
            acc[2] = fmaf(c, v.z, acc[2]); acc[3] = fmaf(c, v.w, acc[3]);
        } else if (V == 2) {
            float2 v = *(const float2*)p;
            acc[0] = fmaf(c, v.x, acc[0]); acc[1] = fmaf(c, v.y, acc[1]);
        } else {
            acc[0] = fmaf(c, p[0], acc[0]);
        }
    }
    float* o = hout + (size_t)gw * 256 + f0;
    float r[V];
#pragma unroll
    for (int q = 0; q < V; q++) r[q] = tanhf(acc[q] + bias[f0 + q]);
    if (V == 4)      *(float4*)o = *(float4*)r;
    else if (V == 2) *(float2*)o = *(float2*)r;
    else             o[0] = r[0];
    if (WRITE_KEYS && V == 1 && lane == 31) g_keys[gw] = r[0];
}

// ---------------- sort-pool + conv5 + maxpool + conv6 + dense ----------------
__global__ void tail_k(const float* __restrict__ w5, const float* __restrict__ b5,
                       const float* __restrict__ w6, const float* __restrict__ b6,
                       const float* __restrict__ dw, const float* __restrict__ db,
                       float* __restrict__ out, int write_idx)
{
    __shared__ float keys[128];
    __shared__ int   sidx[128];
    __shared__ float pooled[32][257];
    __shared__ float r1[16][32];
    __shared__ float m1[16][17];
    __shared__ float z2[384];

    const int g = blockIdx.x;
    const int t = threadIdx.x;

    if (t < 128) {
        keys[t] = g_keys[g * NPER + t];   // compact, coalesced key load
        sidx[t] = t;
    }
    __syncthreads();

    // bitonic sort, descending by key, ties by ascending index (== stable argsort of -key)
    for (int k = 2; k <= 128; k <<= 1) {
        for (int j = k >> 1; j > 0; j >>= 1) {
            if (t < 128) {
                int ixj = t ^ j;
                if (ixj > t) {
                    bool desc = ((t & k) == 0);
                    float ka = keys[t], kb = keys[ixj];
                    int ia = sidx[t], ib = sidx[ixj];
                    bool a_first = (ka > kb) || (ka == kb && ia < ib);
                    bool sw = desc ? !a_first : a_first;
                    if (sw) { keys[t] = kb; keys[ixj] = ka; sidx[t] = ib; sidx[ixj] = ia; }
                }
            }
            __syncthreads();
        }
    }

    // gather pooled [32][256]
    for (int i = t; i < 32 * 256; i += 256) {
        int l = i >> 8, c = i & 255;
        pooled[l][c] = g_h[((size_t)(g * NPER + sidx[l])) * 256 + c];
    }
    __syncthreads();

    // conv5: stride-256 kernel-256 -> per-(co,l) dot over pooled row l
    for (int o = t; o < 512; o += 256) {
        int co = o >> 5, l = o & 31;
        float acc = b5[co];
        const float* wp = w5 + co * 256;
#pragma unroll 8
        for (int k2 = 0; k2 < 256; k2++) acc = fmaf(pooled[l][k2], wp[k2], acc);
        r1[co][l] = fmaxf(acc, 0.f);
    }
    __syncthreads();

    // maxpool k=2 s=2: [16,32] -> [16,16]
    {
        int co = t >> 4, tt = t & 15;
        m1[co][tt] = fmaxf(r1[co][2 * tt], r1[co][2 * tt + 1]);
    }
    __syncthreads();

    // conv6: [16,16] -> [32,12], kernel 5
    for (int o = t; o < 384; o += 256) {
        int co2 = o / 12, tt = o % 12;
        float acc = b6[co2];
#pragma unroll
        for (int ci = 0; ci < 16; ci++) {
            const float* wp = w6 + (co2 * 16 + ci) * 5;
#pragma unroll
            for (int k2 = 0; k2 < 5; k2++) acc = fmaf(m1[ci][tt + k2], wp[k2], acc);
        }
        z2[o] = fmaxf(acc, 0.f);
    }
    __syncthreads();

    // dense 384 -> 27
    if (t < NOUT) {
        float acc = db[t];
        for (int j = 0; j < 384; j++) acc = fmaf(z2[j], dw[j * NOUT + t], acc);
        out[g * NOUT + t] = acc;
    }

    // top-k global indices (cast to output dtype float)
    if (write_idx && t < KTOP) {
        out[NGRAPH * NOUT + g * KTOP + t] = (float)(g * NPER + sidx[t]);
    }
}

// ---------------- host launch ----------------
extern "C" void kernel_launch(void* const* d_in, const int* in_sizes, int n_in,
                              void* d_out, int out_size)
{
    const float* x   = (const float*)d_in[0];
    const int*   ei  = (const int*)d_in[1];      // [2,E]: row = ei, col = ei+E
    const float* W1  = (const float*)d_in[3];
    const float* b1  = (const float*)d_in[4];
    const float* W2  = (const float*)d_in[5];
    const float* b2  = (const float*)d_in[6];
    const float* W3  = (const float*)d_in[7];
    const float* b3  = (const float*)d_in[8];
    const float* W4  = (const float*)d_in[9];
    const float* b4  = (const float*)d_in[10];
    const float* c5w = (const float*)d_in[11];
    const float* c5b = (const float*)d_in[12];
    const float* c6w = (const float*)d_in[13];
    const float* c6b = (const float*)d_in[14];
    const float* dw  = (const float*)d_in[15];
    const float* db  = (const float*)d_in[16];
    float* out = (float*)d_out;

    float *hptr, *xwptr;
    int *degptr;
    cudaGetSymbolAddress((void**)&hptr,  g_h);
    cudaGetSymbolAddress((void**)&xwptr, g_xw);
    cudaGetSymbolAddress((void**)&degptr, g_degI);

    const int* row = ei;
    const int* col = ei + NEDGE;

    const int TB = 256;
    // ----- graph prep (gemm1 interleaved as 4th kernel for ncu visibility;
    //       it is independent of the prep chain) -----
    cudaMemsetAsync(degptr, 0, NNODES * sizeof(int), 0);
    hist_k<<<(NEDGE / 4 + TB - 1) / TB, TB>>>((const int4*)col);
    scan1_k<<<64, 1024>>>();
    scan3_k<<<64, 1024>>>();
    gemm_k<128, 128><<<NNODES / 128, 256>>>(x, FIN, W1, xwptr);   // 4th kernel
    scatter_k<<<(NEDGE + TB - 1) / TB, TB>>>(row, col);

    // ----- layer 1 aggregation -----
    agg_tanh_k<4, false><<<NNODES * 32 / TB, TB>>>(xwptr, b1, hptr + 0);
    // ----- layer 2: 128 -> 64 -----
    gemm_k<64, 128><<<NNODES / 128, 256>>>(hptr + 0, 256, W2, xwptr);
    agg_tanh_k<2, false><<<NNODES * 32 / TB, TB>>>(xwptr, b2, hptr + 128);
    // ----- layer 3: 64 -> 32 -----
    gemm_k<32, 64><<<NNODES / 128, 256>>>(hptr + 128, 256, W3, xwptr);
    agg_tanh_k<1, false><<<NNODES * 32 / TB, TB>>>(xwptr, b3, hptr + 192);
    // ----- layer 4: 32 -> 32 (also emits compact sort keys) -----
    gemm_k<32, 32><<<NNODES / 128, 256>>>(hptr + 192, 256, W4, xwptr);
    agg_tanh_k<1, true><<<NNODES * 32 / TB, TB>>>(xwptr, b4, hptr + 224);

    // ----- sort-pool + conv tail -----
    int write_idx = (out_size >= NGRAPH * NOUT + NGRAPH * KTOP) ? 1 : 0;
    tail_k<<<NGRAPH, 256>>>(c5w, c5b, c6w, c6b, dw, db, out, write_idx);
}

// round 14
// speedup vs baseline: 1.0211x; 1.0211x over previous
#include <cuda_runtime.h>
#include <cuda_bf16.h>
#include <math.h>
#include <stdint.h>

// ---------------- problem constants ----------------
#define NNODES 65536
#define NGRAPH 512
#define NPER   128
#define NEDGE  655360
#define FIN    128
#define KTOP   32
#define NOUT   27

// ---------------- device scratch (no allocs allowed) ----------------
__device__ float g_h[(size_t)NNODES * 256];   // concat features x1|x2|x3|x4
__device__ float g_xw[(size_t)NNODES * 128];  // per-layer X@W scratch
__device__ float g_dinv[NNODES];
__device__ int   g_degI[NNODES];
__device__ int   g_colptr[NNODES + 1];
__device__ int   g_cursor[NNODES];
__device__ int   g_srcs[NEDGE];
__device__ float g_coef[NEDGE];
__device__ float g_keys[NNODES];              // compact sort keys (h[:,255])
__device__ int   g_bsum[64];

// ---------------- f32x2 packed helpers (Blackwell) ----------------
__device__ __forceinline__ void fma2(uint64_t& d, uint64_t a, uint64_t b) {
    asm("fma.rn.f32x2 %0, %1, %2, %0;" : "+l"(d) : "l"(a), "l"(b));
}
__device__ __forceinline__ uint64_t dup2(float a) {
    uint32_t au = __float_as_uint(a);
    uint64_t r;
    asm("mov.b64 %0, {%1, %1};" : "=l"(r) : "r"(au));
    return r;
}

// ---------------- prep kernels ----------------
__global__ void hist_k(const int4* __restrict__ col4) {
    int i = blockIdx.x * blockDim.x + threadIdx.x;
    if (i < NEDGE / 4) {
        int4 c = col4[i];
        atomicAdd(&g_degI[c.x], 1);
        atomicAdd(&g_degI[c.y], 1);
        atomicAdd(&g_degI[c.z], 1);
        atomicAdd(&g_degI[c.w], 1);
    }
}

// ---- parallel exclusive scan over 65536 bins (+ fused dinv & cursor zero) ----
__global__ void scan1_k() {   // 64 blocks x 1024
    __shared__ int s[1024];
    int t = threadIdx.x;
    int idx = blockIdx.x * 1024 + t;
    int v = g_degI[idx];
    g_cursor[idx] = 0;
    g_dinv[idx] = rsqrtf((float)v + 1.0f);
    s[t] = v;
    __syncthreads();
    for (int off = 1; off < 1024; off <<= 1) {
        int tmp = (t >= off) ? s[t - off] : 0;
        __syncthreads();
        s[t] += tmp;
        __syncthreads();
    }
    g_colptr[idx] = s[t] - v;                 // exclusive within block
    if (t == 1023) g_bsum[blockIdx.x] = s[t]; // block total
}

// scan3: each block locally re-scans the 64 block sums (fused scan2)
__global__ void scan3_k() {   // 64 blocks x 1024
    __shared__ int s[64];
    int t = threadIdx.x;
    if (t < 64) s[t] = g_bsum[t];
    __syncthreads();
    for (int off = 1; off < 64; off <<= 1) {
        int v = (t >= off && t < 64) ? s[t - off] : 0;
        __syncthreads();
        if (t < 64) s[t] += v;
        __syncthreads();
    }
    int boff = (blockIdx.x == 0) ? 0 : s[blockIdx.x - 1];
    int idx = blockIdx.x * 1024 + t;
    g_colptr[idx] += boff;
    if (blockIdx.x == 0 && t == 0) g_colptr[NNODES] = s[63];
}

// scalar scatter (latency-bound: keep max thread-level MLP)
__global__ void scatter_k(const int* __restrict__ row, const int* __restrict__ col) {
    int e = blockIdx.x * blockDim.x + threadIdx.x;
    if (e < NEDGE) {
        int c = col[e];
        int r = row[e];
        int p = atomicAdd(&g_cursor[c], 1);
        int pos = g_colptr[c] + p;
        g_srcs[pos] = r;
        g_coef[pos] = g_dinv[r] * g_dinv[c];
    }
}

// ---------------- SGEMM: C[M,TN] = A[M,K](lda) @ B[K,TN] ----------------
// 128xTN tile, BK=16, 256 threads, fma.rn.f32x2 inner loop, double-buffered.
template <int TN, int K>
__global__ __launch_bounds__(256, 2) void gemm_k(const float* __restrict__ A, int lda,
                                                 const float* __restrict__ B,
                                                 float* __restrict__ C)
{
    constexpr int RN = TN / 16;          // 8, 4, or 2
    constexpr int RNH = RN / 2;          // 4, 2, or 1 packed pairs
    constexpr int NB4 = (16 * TN) / 4;   // float4 count per B slab: 512/256/128
    constexpr int NBT = (NB4 + 255) / 256;  // per-thread B float4s: 2/1/1
    __shared__ float As[2][16][128];
    __shared__ float Bs[2][16][TN];

    const int tid = threadIdx.x;
    const int tx = tid & 15;
    const int ty = tid >> 4;
    const int rowBase = blockIdx.x * 128;

    const int ar = tid >> 1;             // 0..127
    const int akk = (tid & 1) * 8;       // 0 or 8

    uint64_t acc2[8][RNH];
#pragma unroll
    for (int i = 0; i < 8; i++)
#pragma unroll
        for (int j = 0; j < RNH; j++) acc2[i][j] = 0ull;

    // prologue: load slab 0
    {
        const float* Ap = A + (size_t)(rowBase + ar) * lda + akk;
        float4 a0 = *(const float4*)(Ap);
        float4 a1 = *(const float4*)(Ap + 4);
        As[0][akk + 0][ar] = a0.x; As[0][akk + 1][ar] = a0.y;
        As[0][akk + 2][ar] = a0.z; As[0][akk + 3][ar] = a0.w;
        As[0][akk + 4][ar] = a1.x; As[0][akk + 5][ar] = a1.y;
        As[0][akk + 6][ar] = a1.z; As[0][akk + 7][ar] = a1.w;
#pragma unroll
        for (int j = tid; j < NB4; j += 256) {
            int kk = (j * 4) / TN, nn = (j * 4) % TN;
            *(float4*)&Bs[0][kk][nn] = *(const float4*)(B + (size_t)kk * TN + nn);
        }
    }
    __syncthreads();

    int buf = 0;
#pragma unroll
    for (int k0 = 0; k0 < K; k0 += 16) {
        float4 av0, av1, bv[NBT];
        const bool more = (k0 + 16) < K;
        if (more) {
            const float* Ap = A + (size_t)(rowBase + ar) * lda + k0 + 16 + akk;
            av0 = *(const float4*)(Ap);
            av1 = *(const float4*)(Ap + 4);
#pragma unroll
            for (int jj = 0; jj < NBT; jj++) {
                int j = tid + jj * 256;
                if (j < NB4) {
                    int kk = (j * 4) / TN, nn = (j * 4) % TN;
                    bv[jj] = *(const float4*)(B + (size_t)(k0 + 16 + kk) * TN + nn);
                }
            }
        }
#pragma unroll
        for (int k = 0; k < 16; k++) {
            float a[8];
            *(float4*)(a)     = *(const float4*)&As[buf][k][ty * 8];
            *(float4*)(a + 4) = *(const float4*)&As[buf][k][ty * 8 + 4];
            float bb[RN];
            if (RN == 8) {
                *(float4*)(bb)     = *(const float4*)&Bs[buf][k][tx * 8];
                *(float4*)(bb + 4) = *(const float4*)&Bs[buf][k][tx * 8 + 4];
            } else if (RN == 4) {
                *(float4*)(bb) = *(const float4*)&Bs[buf][k][tx * 4];
            } else {
                *(float2*)(bb) = *(const float2*)&Bs[buf][k][tx * 2];
            }
            const uint64_t* b2 = (const uint64_t*)bb;
#pragma unroll
            for (int i = 0; i < 8; i++) {
                uint64_t a2 = dup2(a[i]);
#pragma unroll
                for (int j = 0; j < RNH; j++) fma2(acc2[i][j], a2, b2[j]);
            }
        }
        if (more) {
            int nb = buf ^ 1;
            As[nb][akk + 0][ar] = av0.x; As[nb][akk + 1][ar] = av0.y;
            As[nb][akk + 2][ar] = av0.z; As[nb][akk + 3][ar] = av0.w;
            As[nb][akk + 4][ar] = av1.x; As[nb][akk + 5][ar] = av1.y;
            As[nb][akk + 6][ar] = av1.z; As[nb][akk + 7][ar] = av1.w;
#pragma unroll
            for (int jj = 0; jj < NBT; jj++) {
                int j = tid + jj * 256;
                if (j < NB4) {
                    int kk = (j * 4) / TN, nn = (j * 4) % TN;
                    *(float4*)&Bs[nb][kk][nn] = bv[jj];
                }
            }
            __syncthreads();
            buf = nb;
        }
    }

    // epilogue: float4 stores (acc2 pairs are little-endian, match float[RN] layout)
#pragma unroll
    for (int i = 0; i < 8; i++) {
        float* cp = C + (size_t)(rowBase + ty * 8 + i) * TN + tx * RN;
        if (RNH == 4) {
            *(float4*)(cp)     = *(const float4*)&acc2[i][0];
            *(float4*)(cp + 4) = *(const float4*)&acc2[i][2];
        } else if (RNH == 2) {
            *(float4*)(cp) = *(const float4*)&acc2[i][0];
        } else {
            *(uint64_t*)(cp) = acc2[i][0];
        }
    }
}

// ---------------- aggregation + self-loop + bias + tanh ----------------
// warp per node; V = fout/32 features per lane; 4-edge batched gathers.
// NOTE: exact tanhf is REQUIRED — sort keys are tanh outputs; any approximation
// flips argsort order in saturated regions (proven: rel_err 1e-2 in R10).
template <int V, bool WRITE_KEYS>
__global__ void agg_tanh_k(const float* __restrict__ xw,
                           const float* __restrict__ bias,
                           float* __restrict__ hout)   // h + column offset, row stride 256
{
    const int FO = V * 32;
    int gw = (blockIdx.x * blockDim.x + threadIdx.x) >> 5;
    if (gw >= NNODES) return;
    int lane = threadIdx.x & 31;
    int f0 = lane * V;

    float di = g_dinv[gw];
    float acc[V];
    {
        const float* p = xw + (size_t)gw * FO + f0;
        float d2 = di * di;
        if (V == 4) {
            float4 v = *(const float4*)p;
            acc[0] = d2 * v.x; acc[1] = d2 * v.y; acc[2] = d2 * v.z; acc[3] = d2 * v.w;
        } else if (V == 2) {
            float2 v = *(const float2*)p;
            acc[0] = d2 * v.x; acc[1] = d2 * v.y;
        } else {
            acc[0] = d2 * p[0];
        }
    }
    int e0 = g_colptr[gw], e1 = g_colptr[gw + 1];
    int e = e0;
    for (; e + 4 <= e1; e += 4) {
        int s[4]; float c[4];
#pragma unroll
        for (int q = 0; q < 4; q++) { s[q] = g_srcs[e + q]; c[q] = g_coef[e + q]; }
        if (V == 4) {
            float4 v[4];
#pragma unroll
            for (int q = 0; q < 4; q++) v[q] = *(const float4*)(xw + (size_t)s[q] * FO + f0);
#pragma unroll
            for (int q = 0; q < 4; q++) {
                acc[0] = fmaf(c[q], v[q].x, acc[0]); acc[1] = fmaf(c[q], v[q].y, acc[1]);
                acc[2] = fmaf(c[q], v[q].z, acc[2]); acc[3] = fmaf(c[q], v[q].w, acc[3]);
            }
        } else if (V == 2) {
            float2 v[4];
#pragma unroll
            for (int q = 0; q < 4; q++) v[q] = *(const float2*)(xw + (size_t)s[q] * FO + f0);
#pragma unroll
            for (int q = 0; q < 4; q++) {
                acc[0] = fmaf(c[q], v[q].x, acc[0]); acc[1] = fmaf(c[q], v[q].y, acc[1]);
            }
        } else {
            float v[4];
#pragma unroll
            for (int q = 0; q < 4; q++) v[q] = xw[(size_t)s[q] * FO + f0];
#pragma unroll
            for (int q = 0; q < 4; q++) acc[0] = fmaf(c[q], v[q], acc[0]);
        }
    }
    for (; e < e1; e++) {
        int s = g_srcs[e];
        float c = g_coef[e];
        const float* p = xw + (size_t)s * FO + f0;
        if (V == 4) {
            float4 v = *(const float4*)p;
            acc[0] = fmaf(c, v.x, acc[0]); acc[1] = fmaf(c, v.y, acc[1]);
            acc[2] = fmaf(c, v.z, acc[2]); acc[3] = fmaf(c, v.w, acc[3]);
        } else if (V == 2) {
            float2 v = *(const float2*)p;
            acc[0] = fmaf(c, v.x, acc[0]); acc[1] = fmaf(c, v.y, acc[1]);
        } else {
            acc[0] = fmaf(c, p[0], acc[0]);
        }
    }
    float* o = hout + (size_t)gw * 256 + f0;
    float r[V];
#pragma unroll
    for (int q = 0; q < V; q++) r[q] = tanhf(acc[q] + bias[f0 + q]);
    if (V == 4)      *(float4*)o = *(float4*)r;
    else if (V == 2) *(float2*)o = *(float2*)r;
    else             o[0] = r[0];
    if (WRITE_KEYS && V == 1 && lane == 31) g_keys[gw] = r[0];
}

// ---------------- sort-pool + conv5 + maxpool + conv6 + dense ----------------
__global__ void tail_k(const float* __restrict__ w5, const float* __restrict__ b5,
                       const float* __restrict__ w6, const float* __restrict__ b6,
                       const float* __restrict__ dw, const float* __restrict__ db,
                       float* __restrict__ out, int write_idx)
{
    __shared__ float keys[128];
    __shared__ int   sidx[128];
    __shared__ float pooled[32][257];
    __shared__ float r1[16][32];
    __shared__ float m1[16][17];
    __shared__ float z2[384];

    const int g = blockIdx.x;
    const int t = threadIdx.x;

    if (t < 128) {
        keys[t] = g_keys[g * NPER + t];   // compact, coalesced key load
        sidx[t] = t;
    }
    __syncthreads();

    // bitonic sort, descending by key, ties by ascending index (== stable argsort of -key)
    for (int k = 2; k <= 128; k <<= 1) {
        for (int j = k >> 1; j > 0; j >>= 1) {
            if (t < 128) {
                int ixj = t ^ j;
                if (ixj > t) {
                    bool desc = ((t & k) == 0);
                    float ka = keys[t], kb = keys[ixj];
                    int ia = sidx[t], ib = sidx[ixj];
                    bool a_first = (ka > kb) || (ka == kb && ia < ib);
                    bool sw = desc ? !a_first : a_first;
                    if (sw) { keys[t] = kb; keys[ixj] = ka; sidx[t] = ib; sidx[ixj] = ia; }
                }
            }
            __syncthreads();
        }
    }

    // gather pooled [32][256]
    for (int i = t; i < 32 * 256; i += 256) {
        int l = i >> 8, c = i & 255;
        pooled[l][c] = g_h[((size_t)(g * NPER + sidx[l])) * 256 + c];
    }
    __syncthreads();

    // conv5: stride-256 kernel-256 -> per-(co,l) dot over pooled row l
    for (int o = t; o < 512; o += 256) {
        int co = o >> 5, l = o & 31;
        float acc = b5[co];
        const float* wp = w5 + co * 256;
#pragma unroll 8
        for (int k2 = 0; k2 < 256; k2++) acc = fmaf(pooled[l][k2], wp[k2], acc);
        r1[co][l] = fmaxf(acc, 0.f);
    }
    __syncthreads();

    // maxpool k=2 s=2: [16,32] -> [16,16]
    {
        int co = t >> 4, tt = t & 15;
        m1[co][tt] = fmaxf(r1[co][2 * tt], r1[co][2 * tt + 1]);
    }
    __syncthreads();

    // conv6: [16,16] -> [32,12], kernel 5
    for (int o = t; o < 384; o += 256) {
        int co2 = o / 12, tt = o % 12;
        float acc = b6[co2];
#pragma unroll
        for (int ci = 0; ci < 16; ci++) {
            const float* wp = w6 + (co2 * 16 + ci) * 5;
#pragma unroll
            for (int k2 = 0; k2 < 5; k2++) acc = fmaf(m1[ci][tt + k2], wp[k2], acc);
        }
        z2[o] = fmaxf(acc, 0.f);
    }
    __syncthreads();

    // dense 384 -> 27
    if (t < NOUT) {
        float acc = db[t];
        for (int j = 0; j < 384; j++) acc = fmaf(z2[j], dw[j * NOUT + t], acc);
        out[g * NOUT + t] = acc;
    }

    // top-k global indices (cast to output dtype float)
    if (write_idx && t < KTOP) {
        out[NGRAPH * NOUT + g * KTOP + t] = (float)(g * NPER + sidx[t]);
    }
}

// ---------------- host launch ----------------
extern "C" void kernel_launch(void* const* d_in, const int* in_sizes, int n_in,
                              void* d_out, int out_size)
{
    const float* x   = (const float*)d_in[0];
    const int*   ei  = (const int*)d_in[1];      // [2,E]: row = ei, col = ei+E
    const float* W1  = (const float*)d_in[3];
    const float* b1  = (const float*)d_in[4];
    const float* W2  = (const float*)d_in[5];
    const float* b2  = (const float*)d_in[6];
    const float* W3  = (const float*)d_in[7];
    const float* b3  = (const float*)d_in[8];
    const float* W4  = (const float*)d_in[9];
    const float* b4  = (const float*)d_in[10];
    const float* c5w = (const float*)d_in[11];
    const float* c5b = (const float*)d_in[12];
    const float* c6w = (const float*)d_in[13];
    const float* c6b = (const float*)d_in[14];
    const float* dw  = (const float*)d_in[15];
    const float* db  = (const float*)d_in[16];
    float* out = (float*)d_out;

    float *hptr, *xwptr;
    int *degptr;
    cudaGetSymbolAddress((void**)&hptr,  g_h);
    cudaGetSymbolAddress((void**)&xwptr, g_xw);
    cudaGetSymbolAddress((void**)&degptr, g_degI);

    const int* row = ei;
    const int* col = ei + NEDGE;

    const int TB = 256;
    // ----- graph prep (gemm1 kept as 4th kernel for ncu visibility;
    //       it is independent of the prep chain; all serialized on stream 0) -----
    cudaMemsetAsync(degptr, 0, NNODES * sizeof(int), 0);
    hist_k<<<(NEDGE / 4 + TB - 1) / TB, TB>>>((const int4*)col);
    scan1_k<<<64, 1024>>>();
    gemm_k<128, 128><<<NNODES / 128, 256>>>(x, FIN, W1, xwptr);   // 4th kernel
    scan3_k<<<64, 1024>>>();
    scatter_k<<<(NEDGE + TB - 1) / TB, TB>>>(row, col);

    // ----- layer 1 aggregation -----
    agg_tanh_k<4, false><<<NNODES * 32 / TB, TB>>>(xwptr, b1, hptr + 0);
    // ----- layer 2: 128 -> 64 -----
    gemm_k<64, 128><<<NNODES / 128, 256>>>(hptr + 0, 256, W2, xwptr);
    agg_tanh_k<2, false><<<NNODES * 32 / TB, TB>>>(xwptr, b2, hptr + 128);
    // ----- layer 3: 64 -> 32 -----
    gemm_k<32, 64><<<NNODES / 128, 256>>>(hptr + 128, 256, W3, xwptr);
    agg_tanh_k<1, false><<<NNODES * 32 / TB, TB>>>(xwptr, b3, hptr + 192);
    // ----- layer 4: 32 -> 32 (also emits compact sort keys) -----
    gemm_k<32, 32><<<NNODES / 128, 256>>>(hptr + 192, 256, W4, xwptr);
    agg_tanh_k<1, true><<<NNODES * 32 / TB, TB>>>(xwptr, b4, hptr + 224);

    // ----- sort-pool + conv tail -----
    int write_idx = (out_size >= NGRAPH * NOUT + NGRAPH * KTOP) ? 1 : 0;
    tail_k<<<NGRAPH, 256>>>(c5w, c5b, c6w, c6b, dw, db, out, write_idx);
}